// round 8
// baseline (speedup 1.0000x reference)
#include <cuda_runtime.h>
#include <cuda_bf16.h>
#include <math.h>
#include <stdint.h>

// ---------------- scratch (static device globals; no runtime alloc) ----------------
__device__ __nv_bfloat16 g_h1_hi[(size_t)512 * 400 * 256];   // conv1 out hi, [b][pos][ci]
__device__ __nv_bfloat16 g_h1_lo[(size_t)512 * 400 * 256];   // conv1 out lo
__device__ __nv_bfloat16 g_w2_hi[81 * 256 * 256];            // pc_w hi, [kk][co][ci]
__device__ __nv_bfloat16 g_w2_lo[81 * 256 * 256];            // pc_w lo
__device__ float g_h2[512 * 9216];                           // conv2 out [b][co*36+s]
__device__ float g_u[512 * 9216];                            // squashed capsules [b][i][k]
__device__ float g_xhat[(size_t)512 * 10 * 1152 * 16];       // votes [b][o][i][d]
__device__ float g_blog0[512 * 10 * 1152];                   // routing logits ping
__device__ float g_blog1[512 * 10 * 1152];                   // routing logits pong
__device__ float g_c[512 * 10 * 1152];                       // softmax coefficients

// ---------------- PTX helpers (sm_80-era; compile on plain sm_103 target) ----------------
__device__ __forceinline__ uint32_t smem_u32(const void* p) {
    uint32_t a;
    asm("{ .reg .u64 t; cvta.to.shared.u64 t, %1; cvt.u32.u64 %0, t; }" : "=r"(a) : "l"(p));
    return a;
}
__device__ __forceinline__ void ldm_x4(uint32_t* r, uint32_t addr) {
    asm volatile("ldmatrix.sync.aligned.m8n8.x4.shared.b16 {%0,%1,%2,%3}, [%4];"
                 : "=r"(r[0]), "=r"(r[1]), "=r"(r[2]), "=r"(r[3]) : "r"(addr));
}
__device__ __forceinline__ void mma_bf16(float* c, const uint32_t* a, const uint32_t* b) {
    asm volatile("mma.sync.aligned.m16n8k16.row.col.f32.bf16.bf16.f32 "
                 "{%0,%1,%2,%3}, {%4,%5,%6,%7}, {%8,%9}, {%0,%1,%2,%3};"
                 : "+f"(c[0]), "+f"(c[1]), "+f"(c[2]), "+f"(c[3])
                 : "r"(a[0]), "r"(a[1]), "r"(a[2]), "r"(a[3]), "r"(b[0]), "r"(b[1]));
}
__device__ __forceinline__ void cp16(uint32_t dst, const void* src) {
    asm volatile("cp.async.cg.shared.global [%0], [%1], 16;" :: "r"(dst), "l"(src));
}
__device__ __forceinline__ void cp_commit() { asm volatile("cp.async.commit_group;" ::: "memory"); }
__device__ __forceinline__ void cp_wait0()  { asm volatile("cp.async.wait_group 0;" ::: "memory"); }

// ---------------- conv1 (half batch): [256,1,28,28] -> channel-last bf16 hi/lo, ReLU ----------------
__global__ __launch_bounds__(256) void conv1_kernel(const float* __restrict__ x,
                                                    const float* __restrict__ w1,
                                                    const float* __restrict__ b1,
                                                    int b0) {
    __shared__ float xs[784];
    int b  = blockIdx.x + b0;
    int co = threadIdx.x;
    const float* xb = x + (size_t)b * 784;
    for (int idx = co; idx < 784; idx += 256) xs[idx] = xb[idx];
    __syncthreads();

    float bias = b1[co];
    const float* wco = w1 + co * 81;

    for (int oh = 0; oh < 20; oh++) {
        float acc[20];
#pragma unroll
        for (int ow = 0; ow < 20; ow++) acc[ow] = 0.f;

        for (int kh = 0; kh < 9; kh++) {
            float xr[28];
#pragma unroll
            for (int c = 0; c < 28; c++) xr[c] = xs[(oh + kh) * 28 + c];
#pragma unroll
            for (int kw = 0; kw < 9; kw++) {
                float w = __ldg(&wco[kh * 9 + kw]);
#pragma unroll
                for (int ow = 0; ow < 20; ow++) acc[ow] += w * xr[ow + kw];
            }
        }
        size_t base = (((size_t)b * 400) + oh * 20) * 256 + co;
#pragma unroll
        for (int ow = 0; ow < 20; ow++) {
            float v = acc[ow] + bias;
            v = v > 0.f ? v : 0.f;
            __nv_bfloat16 h = __float2bfloat16(v);
            __nv_bfloat16 l = __float2bfloat16(v - __bfloat162float(h));
            g_h1_hi[base + (size_t)ow * 256] = h;
            g_h1_lo[base + (size_t)ow * 256] = l;
        }
    }
}

// ---------------- pc_w convert (coalesced): [co][ci][k] fp32 -> [kk][co][ci] bf16 hi/lo ----------------
__global__ __launch_bounds__(256) void convert_w2(const float* __restrict__ pcw) {
    extern __shared__ float ws[];    // [ci][81]
    int co = blockIdx.x;
    int t = threadIdx.x;
    const float* src = pcw + (size_t)co * 256 * 81;
    for (int idx = t; idx < 256 * 81; idx += 256) ws[idx] = src[idx];
    __syncthreads();
    int ci = t;
    for (int k = 0; k < 81; k++) {
        float v = ws[ci * 81 + k];
        __nv_bfloat16 h = __float2bfloat16(v);
        __nv_bfloat16 l = __float2bfloat16(v - __bfloat162float(h));
        size_t o = ((size_t)k * 256 + co) * 256 + ci;
        g_w2_hi[o] = h;
        g_w2_lo[o] = l;
    }
}

// ---------------- conv2 via HMMA implicit GEMM, cp.async double-buffered (half batch) ----------------
#define LDK 72
#define BUFSZ 110592
#define AHI 0
#define ALO 18432
#define BHI 36864
#define BLO 73728
#define NITER 324
__global__ __launch_bounds__(256, 1) void conv2_mma(const float* __restrict__ pcb, int n0) {
    extern __shared__ char smem[];
    uint32_t sb = smem_u32(smem);
    int tid = threadIdx.x;
    int wid = tid >> 5;
    int lane = tid & 31;
    int mtile = blockIdx.x;          // 0..1   (co block of 128)
    int ntile = blockIdx.y + n0;     // pos block of 256

    int wm = wid & 3;
    int wn = wid >> 2;

    int seg = tid & 7;
    int rbase = tid >> 3;
    uint32_t adst[4];
    uint32_t aoff[4];
#pragma unroll
    for (int j = 0; j < 4; j++) {
        int row = rbase + j * 32;
        adst[j] = (uint32_t)(row * LDK + seg * 8) * 2;
        aoff[j] = (uint32_t)((mtile * 128 + row) * 256 + seg * 8);
    }
    uint32_t bdst[8];
    size_t gb[8];
#pragma unroll
    for (int j = 0; j < 8; j++) {
        int row = rbase + j * 32;
        bdst[j] = (uint32_t)(row * LDK + seg * 8) * 2;
        int p = ntile * 256 + row;
        int b = p / 36;
        int s = p - b * 36;
        int oh = s / 6, ow = s - oh * 6;
        gb[j] = ((size_t)b * 400 + oh * 40 + ow * 2) * 256 + seg * 8;
    }

    float acc[2][16][4];
#pragma unroll
    for (int mt = 0; mt < 2; mt++)
#pragma unroll
        for (int nt = 0; nt < 16; nt++)
#pragma unroll
            for (int j = 0; j < 4; j++) acc[mt][nt][j] = 0.f;

    int rowA = lane & 15;
    int kgA  = (lane >> 4) << 3;
    int rowB = ((lane >> 4) << 3) + (lane & 7);
    int kgB  = ((lane >> 3) & 1) << 3;

#define STAGE(IT, BSEL) do {                                                        \
        int _it = (IT);                                                             \
        int _cb = (_it / 81) << 6;                                                  \
        int _kk = _it - (_it / 81) * 81;                                            \
        int _kh = _kk / 9, _kw = _kk - _kh * 9;                                     \
        uint32_t _bu = sb + (BSEL) * BUFSZ;                                         \
        size_t _abase = ((size_t)_kk * 256) * 256 + _cb;                            \
        size_t _boff = (size_t)(_kh * 20 + _kw) * 256 + _cb;                        \
        _Pragma("unroll")                                                           \
        for (int j = 0; j < 4; j++) {                                               \
            size_t _s = _abase + aoff[j];                                           \
            cp16(_bu + AHI + adst[j], (const char*)g_w2_hi + _s * 2);               \
            cp16(_bu + ALO + adst[j], (const char*)g_w2_lo + _s * 2);               \
        }                                                                           \
        _Pragma("unroll")                                                           \
        for (int j = 0; j < 8; j++) {                                               \
            size_t _s = gb[j] + _boff;                                              \
            cp16(_bu + BHI + bdst[j], (const char*)g_h1_hi + _s * 2);               \
            cp16(_bu + BLO + bdst[j], (const char*)g_h1_lo + _s * 2);               \
        }                                                                           \
    } while (0)

    STAGE(0, 0);
    cp_commit();
    cp_wait0();
    __syncthreads();

    for (int it = 0; it < NITER; it++) {
        if (it + 1 < NITER) { STAGE(it + 1, (it + 1) & 1); cp_commit(); }

        uint32_t bu = sb + (it & 1) * BUFSZ;
#pragma unroll
        for (int ks = 0; ks < 4; ks++) {
            int k0 = ks * 16;
            uint32_t ahi[2][4], alo[2][4];
#pragma unroll
            for (int mt = 0; mt < 2; mt++) {
                uint32_t arow = (uint32_t)((wm * 32 + mt * 16 + rowA) * LDK + k0 + kgA) * 2;
                ldm_x4(ahi[mt], bu + AHI + arow);
                ldm_x4(alo[mt], bu + ALO + arow);
            }
#pragma unroll
            for (int nh = 0; nh < 4; nh++) {
                uint32_t bhi[4][2], blo[4][2];
#pragma unroll
                for (int nq = 0; nq < 2; nq++) {
                    uint32_t brow = (uint32_t)((wn * 128 + nh * 32 + nq * 16 + rowB) * LDK + k0 + kgB) * 2;
                    uint32_t t4[4];
                    ldm_x4(t4, bu + BHI + brow);
                    bhi[2 * nq][0] = t4[0]; bhi[2 * nq][1] = t4[1];
                    bhi[2 * nq + 1][0] = t4[2]; bhi[2 * nq + 1][1] = t4[3];
                    ldm_x4(t4, bu + BLO + brow);
                    blo[2 * nq][0] = t4[0]; blo[2 * nq][1] = t4[1];
                    blo[2 * nq + 1][0] = t4[2]; blo[2 * nq + 1][1] = t4[3];
                }
#pragma unroll
                for (int mt = 0; mt < 2; mt++)
#pragma unroll
                    for (int nq = 0; nq < 4; nq++) {
                        int nt = nh * 4 + nq;
                        mma_bf16(acc[mt][nt], ahi[mt], bhi[nq]);
                        mma_bf16(acc[mt][nt], ahi[mt], blo[nq]);
                        mma_bf16(acc[mt][nt], alo[mt], bhi[nq]);
                    }
            }
        }
        if (it + 1 < NITER) cp_wait0();
        __syncthreads();
    }

    int r0 = lane >> 2, cp = lane & 3;
#pragma unroll
    for (int mt = 0; mt < 2; mt++) {
#pragma unroll
        for (int half = 0; half < 2; half++) {
            int m = wm * 32 + mt * 16 + r0 + half * 8;
            int co = mtile * 128 + m;
            float bias = pcb[co];
#pragma unroll
            for (int nt = 0; nt < 16; nt++) {
#pragma unroll
                for (int e = 0; e < 2; e++) {
                    int p = ntile * 256 + wn * 128 + nt * 8 + 2 * cp + e;
                    int b = p / 36;
                    int s = p - b * 36;
                    g_h2[(size_t)b * 9216 + co * 36 + s] = acc[mt][nt][half * 2 + e] + bias;
                }
            }
        }
    }
}

// ---------------- squash over 8-dim capsules (half batch): g_h2 -> g_u ----------------
__global__ void squash_kernel(int b0) {
    int idx = (size_t)b0 * 1152 + blockIdx.x * 256 + threadIdx.x;   // capsule index
    const float4* p = (const float4*)(g_h2 + (size_t)idx * 8);
    float4 a = p[0], c = p[1];
    float n2 = a.x * a.x + a.y * a.y + a.z * a.z + a.w * a.w +
               c.x * c.x + c.y * c.y + c.z * c.z + c.w * c.w;
    float n = sqrtf(n2);
    float scale = n2 / (1.f + n2) / (n + 1e-8f);
    float4* q = (float4*)(g_u + (size_t)idx * 8);
    a.x *= scale; a.y *= scale; a.z *= scale; a.w *= scale;
    c.x *= scale; c.y *= scale; c.z *= scale; c.w *= scale;
    q[0] = a; q[1] = c;
}

// ---------------- votes, tiled (half batch): caps_w tile in smem, 64 b per block ----------------
__global__ __launch_bounds__(256) void xhat_kernel(const float* __restrict__ cw, int bc0) {
    extern __shared__ float xsm[];
    float* ws = xsm;                    // 128 * 132
    float* us = xsm + 128 * 132;        // 1024

    int o  = blockIdx.x;
    int ic = blockIdx.y;
    int bc = blockIdx.z + bc0;
    int t  = threadIdx.x;

    const float4* src = (const float4*)(cw + ((size_t)o * 1152 + ic * 128) * 128);
    for (int j = t; j < 4096; j += 256) {
        float4 v = src[j];
        int fo = j * 4;
        int il = fo >> 7, rem = fo & 127;
        *(float4*)(ws + il * 132 + rem) = v;
    }
    __syncthreads();

    int d = t & 15;
    int tr = t >> 4;

    for (int bl = 0; bl < 64; bl++) {
        int b = bc * 64 + bl;
        const float4* up = (const float4*)(g_u + ((size_t)b * 1152 + ic * 128) * 8);
        __syncthreads();
        *(float4*)(us + t * 4) = up[t];
        __syncthreads();

        float* xout = g_xhat + (((size_t)(b * 10 + o) * 1152) + ic * 128) * 16;
#pragma unroll
        for (int isub = 0; isub < 8; isub++) {
            int il = isub * 16 + tr;
            const float* wr = ws + il * 132 + d * 8;
            const float* ur = us + il * 8;
            float acc = wr[0] * ur[0] + wr[1] * ur[1] + wr[2] * ur[2] + wr[3] * ur[3]
                      + wr[4] * ur[4] + wr[5] * ur[5] + wr[6] * ur[6] + wr[7] * ur[7];
            xout[il * 16 + d] = acc;
        }
    }
}

// ---------------- softmax over output caps (half batch) ----------------
__global__ __launch_bounds__(256) void softmax_c(const float* __restrict__ blog, int b0) {
    int lidx = blockIdx.x * 256 + threadIdx.x;   // local: 256 b * 1152 i
    int b = b0 + lidx / 1152, i = lidx % 1152;
    const float* blb = blog + (size_t)b * 10 * 1152 + i;
    float vals[10];
    float m = -1e30f;
#pragma unroll
    for (int o = 0; o < 10; o++) {
        vals[o] = blb[(size_t)o * 1152];
        m = fmaxf(m, vals[o]);
    }
    float sum = 0.f;
#pragma unroll
    for (int o = 0; o < 10; o++) { vals[o] = expf(vals[o] - m); sum += vals[o]; }
    float inv = 1.f / sum;
    float* cb = g_c + (size_t)b * 10 * 1152 + i;
#pragma unroll
    for (int o = 0; o < 10; o++) cb[(size_t)o * 1152] = vals[o] * inv;
}

// ---------------- fused routing A+B (half batch) ----------------
template <int MODE>
__global__ __launch_bounds__(256) void routeAB_kernel(const float* __restrict__ blin_g,
                                                      float* __restrict__ blout_g, int bo0) {
    extern __shared__ float sm[];
    float* xs = sm;                 // [1152][17]
    float* cs = sm + 1152 * 17;     // [1152]
    __shared__ float sred[256];
    __shared__ float sd[16];
    __shared__ float sscale;

    int bo = blockIdx.x + bo0;
    int t = threadIdx.x;

    const float4* xg = (const float4*)(g_xhat + (size_t)bo * 1152 * 16);
    for (int j = t; j < 1152 * 4; j += 256) {
        float4 v4 = xg[j];
        int i = j >> 2, q = j & 3;
        float* dst = xs + i * 17 + q * 4;
        dst[0] = v4.x; dst[1] = v4.y; dst[2] = v4.z; dst[3] = v4.w;
    }

    if (MODE == 1) {
        const float* cg = g_c + (size_t)bo * 1152;
        for (int i = t; i < 1152; i += 256) cs[i] = cg[i];
    } else {
        for (int i = t; i < 1152; i += 256) cs[i] = 0.1f;
    }
    __syncthreads();

    int d = t & 15, g = t >> 4;
    float acc = 0.f;
    for (int i = g; i < 1152; i += 16)
        acc += cs[i] * xs[i * 17 + d];
    sred[t] = acc;
    __syncthreads();

    if (t < 16) {
        float s = 0.f;
#pragma unroll
        for (int gg = 0; gg < 16; gg++) s += sred[gg * 16 + t];
        sd[t] = s;
    }
    __syncthreads();

    if (t == 0) {
        float n2 = 0.f;
#pragma unroll
        for (int dd = 0; dd < 16; dd++) n2 += sd[dd] * sd[dd];
        float n = sqrtf(n2);
        sscale = n2 / (1.f + n2) / (n + 1e-8f);
    }
    __syncthreads();

    float scale = sscale;
    const float* blin = blin_g + (size_t)bo * 1152;
    float* blout = blout_g + (size_t)bo * 1152;
    for (int i = t; i < 1152; i += 256) {
        float dot = 0.f;
        const float* xr = xs + i * 17;
#pragma unroll
        for (int dd = 0; dd < 16; dd++) dot += sd[dd] * xr[dd];
        dot *= scale;
        blout[i] = (MODE == 1) ? (blin[i] + dot) : dot;
    }
}

// ---------------- final routing pass (half batch): c -> capsule lengths ----------------
__global__ __launch_bounds__(256) void routeFinal_kernel(float* __restrict__ out, int bo0) {
    __shared__ float cs[1152];
    __shared__ float sred[256];
    __shared__ float sd[16];

    int bo = blockIdx.x + bo0;
    int t = threadIdx.x;

    const float* cg = g_c + (size_t)bo * 1152;
    for (int i = t; i < 1152; i += 256) cs[i] = cg[i];
    __syncthreads();

    int d = t & 15, g = t >> 4;
    float acc = 0.f;
    const float* xb = g_xhat + (size_t)bo * 1152 * 16;
    for (int i = g; i < 1152; i += 16)
        acc += cs[i] * xb[(size_t)i * 16 + d];
    sred[t] = acc;
    __syncthreads();

    if (t < 16) {
        float s = 0.f;
#pragma unroll
        for (int gg = 0; gg < 16; gg++) s += sred[gg * 16 + t];
        sd[t] = s;
    }
    __syncthreads();

    if (t == 0) {
        float n2 = 0.f;
#pragma unroll
        for (int dd = 0; dd < 16; dd++) n2 += sd[dd] * sd[dd];
        float n = sqrtf(n2);
        float scale = n2 / (1.f + n2) / (n + 1e-8f);
        out[bo] = scale * n;
    }
}

// ---------------- launch: two-stream software pipeline over batch halves ----------------
extern "C" void kernel_launch(void* const* d_in, const int* in_sizes, int n_in,
                              void* d_out, int out_size) {
    const float* x   = (const float*)d_in[0];
    const float* w1  = (const float*)d_in[1];
    const float* b1  = (const float*)d_in[2];
    const float* w2  = (const float*)d_in[3];
    const float* b2  = (const float*)d_in[4];
    const float* cw  = (const float*)d_in[5];
    float* out = (float*)d_out;

    const int CONV2_SMEM = 2 * BUFSZ;                    // 221184 B
    const int ROUTE_SMEM = (1152 * 17 + 1152) * 4;       // 82944 B
    const int W2_SMEM    = 256 * 81 * 4;                 // 82944 B
    const int XHAT_SMEM  = (128 * 132 + 1024) * 4;       // 71680 B
    cudaFuncSetAttribute(conv2_mma, cudaFuncAttributeMaxDynamicSharedMemorySize, CONV2_SMEM);
    cudaFuncSetAttribute(convert_w2, cudaFuncAttributeMaxDynamicSharedMemorySize, W2_SMEM);
    cudaFuncSetAttribute(xhat_kernel, cudaFuncAttributeMaxDynamicSharedMemorySize, XHAT_SMEM);
    cudaFuncSetAttribute(routeAB_kernel<0>, cudaFuncAttributeMaxDynamicSharedMemorySize, ROUTE_SMEM);
    cudaFuncSetAttribute(routeAB_kernel<1>, cudaFuncAttributeMaxDynamicSharedMemorySize, ROUTE_SMEM);

    float *blog0, *blog1;
    cudaGetSymbolAddress((void**)&blog0, g_blog0);
    cudaGetSymbolAddress((void**)&blog1, g_blog1);

    // side stream + events (created per call; host-side only, no device allocation)
    cudaStream_t s2;
    cudaStreamCreateWithFlags(&s2, cudaStreamNonBlocking);
    cudaEvent_t evStart, evB, evC;
    cudaEventCreateWithFlags(&evStart, cudaEventDisableTiming);
    cudaEventCreateWithFlags(&evB, cudaEventDisableTiming);
    cudaEventCreateWithFlags(&evC, cudaEventDisableTiming);

    // fork
    cudaEventRecord(evStart, 0);
    cudaStreamWaitEvent(s2, evStart, 0);

    // ---- s0: half0 conv path ----
    convert_w2<<<256, 256, W2_SMEM>>>(w2);
    conv1_kernel<<<256, 256>>>(x, w1, b1, 0);
    conv2_mma<<<dim3(2, 36), 256, CONV2_SMEM>>>(b2, 0);
    cudaEventRecord(evB, 0);

    // ---- s2: conv1(h1) overlaps conv2(h0); conv2(h1) overlaps post(h0) ----
    conv1_kernel<<<256, 256, 0, s2>>>(x, w1, b1, 256);
    cudaStreamWaitEvent(s2, evB, 0);
    conv2_mma<<<dim3(2, 36), 256, CONV2_SMEM, s2>>>(b2, 36);
    cudaEventRecord(evC, s2);

    // ---- s0: post half0 (concurrent with conv2(h1)) ----
    squash_kernel<<<1152, 256>>>(0);
    xhat_kernel<<<dim3(10, 9, 4), 256, XHAT_SMEM>>>(cw, 0);
    routeAB_kernel<0><<<2560, 256, ROUTE_SMEM>>>(blog0, blog0, 0);
    softmax_c<<<1152, 256>>>(blog0, 0);
    routeAB_kernel<1><<<2560, 256, ROUTE_SMEM>>>(blog0, blog1, 0);
    softmax_c<<<1152, 256>>>(blog1, 0);
    routeFinal_kernel<<<2560, 256>>>(out, 0);

    // ---- join, then post half1 on s0 ----
    cudaStreamWaitEvent(0, evC, 0);
    squash_kernel<<<1152, 256>>>(256);
    xhat_kernel<<<dim3(10, 9, 4), 256, XHAT_SMEM>>>(cw, 4);
    routeAB_kernel<0><<<2560, 256, ROUTE_SMEM>>>(blog0, blog0, 2560);
    softmax_c<<<1152, 256>>>(blog0, 256);
    routeAB_kernel<1><<<2560, 256, ROUTE_SMEM>>>(blog0, blog1, 2560);
    softmax_c<<<1152, 256>>>(blog1, 256);
    routeFinal_kernel<<<2560, 256>>>(out, 2560);
}

// round 9
// speedup vs baseline: 1.3765x; 1.3765x over previous
#include <cuda_runtime.h>
#include <cuda_bf16.h>
#include <math.h>
#include <stdint.h>

// ---------------- scratch (static device globals; no runtime alloc) ----------------
__device__ __nv_bfloat16 g_h1_hi[(size_t)512 * 400 * 256];   // conv1 out hi, [b][pos][ci]
__device__ __nv_bfloat16 g_h1_lo[(size_t)512 * 400 * 256];   // conv1 out lo
__device__ __nv_bfloat16 g_w2_hi[81 * 256 * 256];            // pc_w hi, [kk][co][ci]
__device__ __nv_bfloat16 g_w2_lo[81 * 256 * 256];            // pc_w lo
__device__ float g_h2[512 * 9216];                           // conv2 out [b][co*36+s]
__device__ float g_u[512 * 9216];                            // squashed capsules [b][i][k]
__device__ float g_xhat[(size_t)512 * 10 * 1152 * 16];       // votes [b][o][i][d]
__device__ float g_blog0[512 * 10 * 1152];                   // routing logits ping
__device__ float g_blog1[512 * 10 * 1152];                   // routing logits pong
__device__ float g_c[512 * 10 * 1152];                       // softmax coefficients

// ---------------- PTX helpers (sm_80-era; compile on plain sm_103 target) ----------------
__device__ __forceinline__ uint32_t smem_u32(const void* p) {
    uint32_t a;
    asm("{ .reg .u64 t; cvta.to.shared.u64 t, %1; cvt.u32.u64 %0, t; }" : "=r"(a) : "l"(p));
    return a;
}
__device__ __forceinline__ void ldm_x4(uint32_t* r, uint32_t addr) {
    asm volatile("ldmatrix.sync.aligned.m8n8.x4.shared.b16 {%0,%1,%2,%3}, [%4];"
                 : "=r"(r[0]), "=r"(r[1]), "=r"(r[2]), "=r"(r[3]) : "r"(addr));
}
__device__ __forceinline__ void mma_bf16(float* c, const uint32_t* a, const uint32_t* b) {
    asm volatile("mma.sync.aligned.m16n8k16.row.col.f32.bf16.bf16.f32 "
                 "{%0,%1,%2,%3}, {%4,%5,%6,%7}, {%8,%9}, {%0,%1,%2,%3};"
                 : "+f"(c[0]), "+f"(c[1]), "+f"(c[2]), "+f"(c[3])
                 : "r"(a[0]), "r"(a[1]), "r"(a[2]), "r"(a[3]), "r"(b[0]), "r"(b[1]));
}
__device__ __forceinline__ void cp16(uint32_t dst, const void* src) {
    asm volatile("cp.async.cg.shared.global [%0], [%1], 16;" :: "r"(dst), "l"(src));
}
__device__ __forceinline__ void cp_commit() { asm volatile("cp.async.commit_group;" ::: "memory"); }
__device__ __forceinline__ void cp_wait0()  { asm volatile("cp.async.wait_group 0;" ::: "memory"); }

// ---------------- conv1: [512,1,28,28] -> channel-last bf16 hi/lo, ReLU ----------------
// grid (512 b, 2 oh-halves): each block computes 10 oh rows -> 2x parallelism vs R7.
__global__ __launch_bounds__(256) void conv1_kernel(const float* __restrict__ x,
                                                    const float* __restrict__ w1,
                                                    const float* __restrict__ b1) {
    __shared__ float xs[784];
    int b  = blockIdx.x;
    int oh0 = blockIdx.y * 10;
    int co = threadIdx.x;
    const float* xb = x + (size_t)b * 784;
    for (int idx = co; idx < 784; idx += 256) xs[idx] = xb[idx];
    __syncthreads();

    float bias = b1[co];
    const float* wco = w1 + co * 81;

    for (int oh = oh0; oh < oh0 + 10; oh++) {
        float acc[20];
#pragma unroll
        for (int ow = 0; ow < 20; ow++) acc[ow] = 0.f;

        for (int kh = 0; kh < 9; kh++) {
            float xr[28];
#pragma unroll
            for (int c = 0; c < 28; c++) xr[c] = xs[(oh + kh) * 28 + c];
#pragma unroll
            for (int kw = 0; kw < 9; kw++) {
                float w = __ldg(&wco[kh * 9 + kw]);
#pragma unroll
                for (int ow = 0; ow < 20; ow++) acc[ow] += w * xr[ow + kw];
            }
        }
        size_t base = (((size_t)b * 400) + oh * 20) * 256 + co;
#pragma unroll
        for (int ow = 0; ow < 20; ow++) {
            float v = acc[ow] + bias;
            v = v > 0.f ? v : 0.f;
            __nv_bfloat16 h = __float2bfloat16(v);
            __nv_bfloat16 l = __float2bfloat16(v - __bfloat162float(h));
            g_h1_hi[base + (size_t)ow * 256] = h;
            g_h1_lo[base + (size_t)ow * 256] = l;
        }
    }
}

// ---------------- pc_w convert (coalesced): [co][ci][k] fp32 -> [kk][co][ci] bf16 hi/lo ----------------
__global__ __launch_bounds__(256) void convert_w2(const float* __restrict__ pcw) {
    extern __shared__ float ws[];    // [ci][81]
    int co = blockIdx.x;
    int t = threadIdx.x;
    const float* src = pcw + (size_t)co * 256 * 81;
    for (int idx = t; idx < 256 * 81; idx += 256) ws[idx] = src[idx];
    __syncthreads();
    int ci = t;
    for (int k = 0; k < 81; k++) {
        float v = ws[ci * 81 + k];
        __nv_bfloat16 h = __float2bfloat16(v);
        __nv_bfloat16 l = __float2bfloat16(v - __bfloat162float(h));
        size_t o = ((size_t)k * 256 + co) * 256 + ci;
        g_w2_hi[o] = h;
        g_w2_lo[o] = l;
    }
}

// ---------------- conv2 via HMMA implicit GEMM, cp.async double-buffered ----------------
#define LDK 72
#define BUFSZ 110592
#define AHI 0
#define ALO 18432
#define BHI 36864
#define BLO 73728
#define NITER 324
__global__ __launch_bounds__(256, 1) void conv2_mma(const float* __restrict__ pcb) {
    extern __shared__ char smem[];
    uint32_t sb = smem_u32(smem);
    int tid = threadIdx.x;
    int wid = tid >> 5;
    int lane = tid & 31;
    int mtile = blockIdx.x;      // 0..1   (co block of 128)
    int ntile = blockIdx.y;      // 0..71  (pos block of 256)

    int wm = wid & 3;
    int wn = wid >> 2;

    int seg = tid & 7;
    int rbase = tid >> 3;
    uint32_t adst[4];
    uint32_t aoff[4];
#pragma unroll
    for (int j = 0; j < 4; j++) {
        int row = rbase + j * 32;
        adst[j] = (uint32_t)(row * LDK + seg * 8) * 2;
        aoff[j] = (uint32_t)((mtile * 128 + row) * 256 + seg * 8);
    }
    uint32_t bdst[8];
    size_t gb[8];
#pragma unroll
    for (int j = 0; j < 8; j++) {
        int row = rbase + j * 32;
        bdst[j] = (uint32_t)(row * LDK + seg * 8) * 2;
        int p = ntile * 256 + row;
        int b = p / 36;
        int s = p - b * 36;
        int oh = s / 6, ow = s - oh * 6;
        gb[j] = ((size_t)b * 400 + oh * 40 + ow * 2) * 256 + seg * 8;
    }

    float acc[2][16][4];
#pragma unroll
    for (int mt = 0; mt < 2; mt++)
#pragma unroll
        for (int nt = 0; nt < 16; nt++)
#pragma unroll
            for (int j = 0; j < 4; j++) acc[mt][nt][j] = 0.f;

    int rowA = lane & 15;
    int kgA  = (lane >> 4) << 3;
    int rowB = ((lane >> 4) << 3) + (lane & 7);
    int kgB  = ((lane >> 3) & 1) << 3;

#define STAGE(IT, BSEL) do {                                                        \
        int _it = (IT);                                                             \
        int _cb = (_it / 81) << 6;                                                  \
        int _kk = _it - (_it / 81) * 81;                                            \
        int _kh = _kk / 9, _kw = _kk - _kh * 9;                                     \
        uint32_t _bu = sb + (BSEL) * BUFSZ;                                         \
        size_t _abase = ((size_t)_kk * 256) * 256 + _cb;                            \
        size_t _boff = (size_t)(_kh * 20 + _kw) * 256 + _cb;                        \
        _Pragma("unroll")                                                           \
        for (int j = 0; j < 4; j++) {                                               \
            size_t _s = _abase + aoff[j];                                           \
            cp16(_bu + AHI + adst[j], (const char*)g_w2_hi + _s * 2);               \
            cp16(_bu + ALO + adst[j], (const char*)g_w2_lo + _s * 2);               \
        }                                                                           \
        _Pragma("unroll")                                                           \
        for (int j = 0; j < 8; j++) {                                               \
            size_t _s = gb[j] + _boff;                                              \
            cp16(_bu + BHI + bdst[j], (const char*)g_h1_hi + _s * 2);               \
            cp16(_bu + BLO + bdst[j], (const char*)g_h1_lo + _s * 2);               \
        }                                                                           \
    } while (0)

    STAGE(0, 0);
    cp_commit();
    cp_wait0();
    __syncthreads();

    for (int it = 0; it < NITER; it++) {
        if (it + 1 < NITER) { STAGE(it + 1, (it + 1) & 1); cp_commit(); }

        uint32_t bu = sb + (it & 1) * BUFSZ;
#pragma unroll
        for (int ks = 0; ks < 4; ks++) {
            int k0 = ks * 16;
            uint32_t ahi[2][4], alo[2][4];
#pragma unroll
            for (int mt = 0; mt < 2; mt++) {
                uint32_t arow = (uint32_t)((wm * 32 + mt * 16 + rowA) * LDK + k0 + kgA) * 2;
                ldm_x4(ahi[mt], bu + AHI + arow);
                ldm_x4(alo[mt], bu + ALO + arow);
            }
#pragma unroll
            for (int nh = 0; nh < 4; nh++) {
                uint32_t bhi[4][2], blo[4][2];
#pragma unroll
                for (int nq = 0; nq < 2; nq++) {
                    uint32_t brow = (uint32_t)((wn * 128 + nh * 32 + nq * 16 + rowB) * LDK + k0 + kgB) * 2;
                    uint32_t t4[4];
                    ldm_x4(t4, bu + BHI + brow);
                    bhi[2 * nq][0] = t4[0]; bhi[2 * nq][1] = t4[1];
                    bhi[2 * nq + 1][0] = t4[2]; bhi[2 * nq + 1][1] = t4[3];
                    ldm_x4(t4, bu + BLO + brow);
                    blo[2 * nq][0] = t4[0]; blo[2 * nq][1] = t4[1];
                    blo[2 * nq + 1][0] = t4[2]; blo[2 * nq + 1][1] = t4[3];
                }
#pragma unroll
                for (int mt = 0; mt < 2; mt++)
#pragma unroll
                    for (int nq = 0; nq < 4; nq++) {
                        int nt = nh * 4 + nq;
                        mma_bf16(acc[mt][nt], ahi[mt], bhi[nq]);
                        mma_bf16(acc[mt][nt], ahi[mt], blo[nq]);
                        mma_bf16(acc[mt][nt], alo[mt], bhi[nq]);
                    }
            }
        }
        if (it + 1 < NITER) cp_wait0();
        __syncthreads();
    }

    int r0 = lane >> 2, cp = lane & 3;
#pragma unroll
    for (int mt = 0; mt < 2; mt++) {
#pragma unroll
        for (int half = 0; half < 2; half++) {
            int m = wm * 32 + mt * 16 + r0 + half * 8;
            int co = mtile * 128 + m;
            float bias = pcb[co];
#pragma unroll
            for (int nt = 0; nt < 16; nt++) {
#pragma unroll
                for (int e = 0; e < 2; e++) {
                    int p = ntile * 256 + wn * 128 + nt * 8 + 2 * cp + e;
                    int b = p / 36;
                    int s = p - b * 36;
                    g_h2[(size_t)b * 9216 + co * 36 + s] = acc[mt][nt][half * 2 + e] + bias;
                }
            }
        }
    }
}

// ---------------- squash over 8-dim capsules: g_h2 -> g_u ----------------
__global__ void squash_kernel() {
    int idx = blockIdx.x * 256 + threadIdx.x;
    if (idx >= 512 * 1152) return;
    const float4* p = (const float4*)(g_h2 + (size_t)idx * 8);
    float4 a = p[0], c = p[1];
    float n2 = a.x * a.x + a.y * a.y + a.z * a.z + a.w * a.w +
               c.x * c.x + c.y * c.y + c.z * c.z + c.w * c.w;
    float n = sqrtf(n2);
    float scale = n2 / (1.f + n2) / (n + 1e-8f);
    float4* q = (float4*)(g_u + (size_t)idx * 8);
    a.x *= scale; a.y *= scale; a.z *= scale; a.w *= scale;
    c.x *= scale; c.y *= scale; c.z *= scale; c.w *= scale;
    q[0] = a; q[1] = c;
}

// ---------------- votes, tiled: caps_w tile resident in smem, 64 b per block ----------------
__global__ __launch_bounds__(256) void xhat_kernel(const float* __restrict__ cw) {
    extern __shared__ float xsm[];
    float* ws = xsm;                    // 128 * 132
    float* us = xsm + 128 * 132;        // 1024

    int o  = blockIdx.x;
    int ic = blockIdx.y;
    int bc = blockIdx.z;
    int t  = threadIdx.x;

    const float4* src = (const float4*)(cw + ((size_t)o * 1152 + ic * 128) * 128);
    for (int j = t; j < 4096; j += 256) {
        float4 v = src[j];
        int fo = j * 4;
        int il = fo >> 7, rem = fo & 127;
        *(float4*)(ws + il * 132 + rem) = v;
    }
    __syncthreads();

    int d = t & 15;
    int tr = t >> 4;

    for (int bl = 0; bl < 64; bl++) {
        int b = bc * 64 + bl;
        const float4* up = (const float4*)(g_u + ((size_t)b * 1152 + ic * 128) * 8);
        __syncthreads();
        *(float4*)(us + t * 4) = up[t];
        __syncthreads();

        float* xout = g_xhat + (((size_t)(b * 10 + o) * 1152) + ic * 128) * 16;
#pragma unroll
        for (int isub = 0; isub < 8; isub++) {
            int il = isub * 16 + tr;
            const float* wr = ws + il * 132 + d * 8;
            const float* ur = us + il * 8;
            float acc = wr[0] * ur[0] + wr[1] * ur[1] + wr[2] * ur[2] + wr[3] * ur[3]
                      + wr[4] * ur[4] + wr[5] * ur[5] + wr[6] * ur[6] + wr[7] * ur[7];
            xout[il * 16 + d] = acc;
        }
    }
}

// ---------------- softmax over output caps: c[b,o,i] = softmax_o(blog[b,o,i]) ----------------
__global__ __launch_bounds__(256) void softmax_c(const float* __restrict__ blog) {
    int idx = blockIdx.x * 256 + threadIdx.x;   // b*1152 + i
    if (idx >= 512 * 1152) return;
    int b = idx / 1152, i = idx - b * 1152;
    const float* blb = blog + (size_t)b * 10 * 1152 + i;
    float vals[10];
    float m = -1e30f;
#pragma unroll
    for (int o = 0; o < 10; o++) {
        vals[o] = blb[(size_t)o * 1152];
        m = fmaxf(m, vals[o]);
    }
    float sum = 0.f;
#pragma unroll
    for (int o = 0; o < 10; o++) { vals[o] = expf(vals[o] - m); sum += vals[o]; }
    float inv = 1.f / sum;
    float* cb = g_c + (size_t)b * 10 * 1152 + i;
#pragma unroll
    for (int o = 0; o < 10; o++) cb[(size_t)o * 1152] = vals[o] * inv;
}

// ---------------- fused routing A+B: c -> v (squash) -> logit update ----------------
template <int MODE>
__global__ __launch_bounds__(256) void routeAB_kernel(const float* __restrict__ blin_g,
                                                      float* __restrict__ blout_g) {
    extern __shared__ float sm[];
    float* xs = sm;                 // [1152][17]
    float* cs = sm + 1152 * 17;     // [1152]
    __shared__ float sred[256];
    __shared__ float sd[16];
    __shared__ float sscale;

    int bo = blockIdx.x;
    int t = threadIdx.x;

    const float4* xg = (const float4*)(g_xhat + (size_t)bo * 1152 * 16);
    for (int j = t; j < 1152 * 4; j += 256) {
        float4 v4 = xg[j];
        int i = j >> 2, q = j & 3;
        float* dst = xs + i * 17 + q * 4;
        dst[0] = v4.x; dst[1] = v4.y; dst[2] = v4.z; dst[3] = v4.w;
    }

    if (MODE == 1) {
        const float* cg = g_c + (size_t)bo * 1152;
        for (int i = t; i < 1152; i += 256) cs[i] = cg[i];
    } else {
        for (int i = t; i < 1152; i += 256) cs[i] = 0.1f;
    }
    __syncthreads();

    int d = t & 15, g = t >> 4;
    float acc = 0.f;
    for (int i = g; i < 1152; i += 16)
        acc += cs[i] * xs[i * 17 + d];
    sred[t] = acc;
    __syncthreads();

    if (t < 16) {
        float s = 0.f;
#pragma unroll
        for (int gg = 0; gg < 16; gg++) s += sred[gg * 16 + t];
        sd[t] = s;
    }
    __syncthreads();

    if (t == 0) {
        float n2 = 0.f;
#pragma unroll
        for (int dd = 0; dd < 16; dd++) n2 += sd[dd] * sd[dd];
        float n = sqrtf(n2);
        sscale = n2 / (1.f + n2) / (n + 1e-8f);
    }
    __syncthreads();

    float scale = sscale;
    const float* blin = blin_g + (size_t)bo * 1152;
    float* blout = blout_g + (size_t)bo * 1152;
    for (int i = t; i < 1152; i += 256) {
        float dot = 0.f;
        const float* xr = xs + i * 17;
#pragma unroll
        for (int dd = 0; dd < 16; dd++) dot += sd[dd] * xr[dd];
        dot *= scale;
        blout[i] = (MODE == 1) ? (blin[i] + dot) : dot;
    }
}

// ---------------- final routing pass: c (precomputed) -> capsule lengths ----------------
__global__ __launch_bounds__(256) void routeFinal_kernel(float* __restrict__ out) {
    __shared__ float cs[1152];
    __shared__ float sred[256];
    __shared__ float sd[16];

    int bo = blockIdx.x;
    int t = threadIdx.x;

    const float* cg = g_c + (size_t)bo * 1152;
    for (int i = t; i < 1152; i += 256) cs[i] = cg[i];
    __syncthreads();

    int d = t & 15, g = t >> 4;
    float acc = 0.f;
    const float* xb = g_xhat + (size_t)bo * 1152 * 16;
    for (int i = g; i < 1152; i += 16)
        acc += cs[i] * xb[(size_t)i * 16 + d];
    sred[t] = acc;
    __syncthreads();

    if (t < 16) {
        float s = 0.f;
#pragma unroll
        for (int gg = 0; gg < 16; gg++) s += sred[gg * 16 + t];
        sd[t] = s;
    }
    __syncthreads();

    if (t == 0) {
        float n2 = 0.f;
#pragma unroll
        for (int dd = 0; dd < 16; dd++) n2 += sd[dd] * sd[dd];
        float n = sqrtf(n2);
        float scale = n2 / (1.f + n2) / (n + 1e-8f);
        out[bo] = scale * n;
    }
}

// ---------------- launch (single stream; R7 structure) ----------------
extern "C" void kernel_launch(void* const* d_in, const int* in_sizes, int n_in,
                              void* d_out, int out_size) {
    const float* x   = (const float*)d_in[0];
    const float* w1  = (const float*)d_in[1];
    const float* b1  = (const float*)d_in[2];
    const float* w2  = (const float*)d_in[3];
    const float* b2  = (const float*)d_in[4];
    const float* cw  = (const float*)d_in[5];
    float* out = (float*)d_out;

    const int CONV2_SMEM = 2 * BUFSZ;                    // 221184 B
    const int ROUTE_SMEM = (1152 * 17 + 1152) * 4;       // 82944 B
    const int W2_SMEM    = 256 * 81 * 4;                 // 82944 B
    const int XHAT_SMEM  = (128 * 132 + 1024) * 4;       // 71680 B
    cudaFuncSetAttribute(conv2_mma, cudaFuncAttributeMaxDynamicSharedMemorySize, CONV2_SMEM);
    cudaFuncSetAttribute(convert_w2, cudaFuncAttributeMaxDynamicSharedMemorySize, W2_SMEM);
    cudaFuncSetAttribute(xhat_kernel, cudaFuncAttributeMaxDynamicSharedMemorySize, XHAT_SMEM);
    cudaFuncSetAttribute(routeAB_kernel<0>, cudaFuncAttributeMaxDynamicSharedMemorySize, ROUTE_SMEM);
    cudaFuncSetAttribute(routeAB_kernel<1>, cudaFuncAttributeMaxDynamicSharedMemorySize, ROUTE_SMEM);

    float *blog0, *blog1;
    cudaGetSymbolAddress((void**)&blog0, g_blog0);
    cudaGetSymbolAddress((void**)&blog1, g_blog1);

    conv1_kernel<<<dim3(512, 2), 256>>>(x, w1, b1);
    convert_w2<<<256, 256, W2_SMEM>>>(w2);
    conv2_mma<<<dim3(2, 72), 256, CONV2_SMEM>>>(b2);
    squash_kernel<<<(512 * 1152 + 255) / 256, 256>>>();
    xhat_kernel<<<dim3(10, 9, 8), 256, XHAT_SMEM>>>(cw);

    routeAB_kernel<0><<<5120, 256, ROUTE_SMEM>>>(blog0, blog0);   // iter 0: uniform c
    softmax_c<<<(512 * 1152 + 255) / 256, 256>>>(blog0);
    routeAB_kernel<1><<<5120, 256, ROUTE_SMEM>>>(blog0, blog1);   // iter 1
    softmax_c<<<(512 * 1152 + 255) / 256, 256>>>(blog1);
    routeFinal_kernel<<<5120, 256>>>(out);                        // iter 2: lengths
}

// round 10
// speedup vs baseline: 1.4441x; 1.0491x over previous
#include <cuda_runtime.h>
#include <cuda_bf16.h>
#include <cuda_fp16.h>
#include <math.h>
#include <stdint.h>

// ---------------- scratch (static device globals; no runtime alloc) ----------------
__device__ __nv_bfloat16 g_h1_hi[(size_t)512 * 400 * 256];   // conv1 out hi, [b][pos][ci]
__device__ __nv_bfloat16 g_h1_lo[(size_t)512 * 400 * 256];   // conv1 out lo
__device__ __nv_bfloat16 g_w2_hi[81 * 256 * 256];            // pc_w hi, [kk][co][ci]
__device__ __nv_bfloat16 g_w2_lo[81 * 256 * 256];            // pc_w lo
__device__ float g_h2[512 * 9216];                           // conv2 out [b][co*36+s]
__device__ float g_u[512 * 9216];                            // squashed capsules [b][i][k]
__device__ __half g_xhat[(size_t)512 * 10 * 1152 * 16];      // votes [b][o][i][d] (fp16)
__device__ float g_blog0[512 * 10 * 1152];                   // routing logits ping
__device__ float g_blog1[512 * 10 * 1152];                   // routing logits pong
__device__ float g_c[512 * 10 * 1152];                       // softmax coefficients

// ---------------- PTX helpers (sm_80-era; compile on plain sm_103 target) ----------------
__device__ __forceinline__ uint32_t smem_u32(const void* p) {
    uint32_t a;
    asm("{ .reg .u64 t; cvta.to.shared.u64 t, %1; cvt.u32.u64 %0, t; }" : "=r"(a) : "l"(p));
    return a;
}
__device__ __forceinline__ void ldm_x4(uint32_t* r, uint32_t addr) {
    asm volatile("ldmatrix.sync.aligned.m8n8.x4.shared.b16 {%0,%1,%2,%3}, [%4];"
                 : "=r"(r[0]), "=r"(r[1]), "=r"(r[2]), "=r"(r[3]) : "r"(addr));
}
__device__ __forceinline__ void mma_bf16(float* c, const uint32_t* a, const uint32_t* b) {
    asm volatile("mma.sync.aligned.m16n8k16.row.col.f32.bf16.bf16.f32 "
                 "{%0,%1,%2,%3}, {%4,%5,%6,%7}, {%8,%9}, {%0,%1,%2,%3};"
                 : "+f"(c[0]), "+f"(c[1]), "+f"(c[2]), "+f"(c[3])
                 : "r"(a[0]), "r"(a[1]), "r"(a[2]), "r"(a[3]), "r"(b[0]), "r"(b[1]));
}
__device__ __forceinline__ void cp16(uint32_t dst, const void* src) {
    asm volatile("cp.async.cg.shared.global [%0], [%1], 16;" :: "r"(dst), "l"(src));
}
__device__ __forceinline__ void cp_commit() { asm volatile("cp.async.commit_group;" ::: "memory"); }
__device__ __forceinline__ void cp_wait0()  { asm volatile("cp.async.wait_group 0;" ::: "memory"); }

// ---------------- conv1: [512,1,28,28] -> channel-last bf16 hi/lo, ReLU ----------------
__global__ __launch_bounds__(256) void conv1_kernel(const float* __restrict__ x,
                                                    const float* __restrict__ w1,
                                                    const float* __restrict__ b1) {
    __shared__ float xs[784];
    int b  = blockIdx.x;
    int oh0 = blockIdx.y * 10;
    int co = threadIdx.x;
    const float* xb = x + (size_t)b * 784;
    for (int idx = co; idx < 784; idx += 256) xs[idx] = xb[idx];
    __syncthreads();

    float bias = b1[co];
    const float* wco = w1 + co * 81;

    for (int oh = oh0; oh < oh0 + 10; oh++) {
        float acc[20];
#pragma unroll
        for (int ow = 0; ow < 20; ow++) acc[ow] = 0.f;

        for (int kh = 0; kh < 9; kh++) {
            float xr[28];
#pragma unroll
            for (int c = 0; c < 28; c++) xr[c] = xs[(oh + kh) * 28 + c];
#pragma unroll
            for (int kw = 0; kw < 9; kw++) {
                float w = __ldg(&wco[kh * 9 + kw]);
#pragma unroll
                for (int ow = 0; ow < 20; ow++) acc[ow] += w * xr[ow + kw];
            }
        }
        size_t base = (((size_t)b * 400) + oh * 20) * 256 + co;
#pragma unroll
        for (int ow = 0; ow < 20; ow++) {
            float v = acc[ow] + bias;
            v = v > 0.f ? v : 0.f;
            __nv_bfloat16 h = __float2bfloat16(v);
            __nv_bfloat16 l = __float2bfloat16(v - __bfloat162float(h));
            g_h1_hi[base + (size_t)ow * 256] = h;
            g_h1_lo[base + (size_t)ow * 256] = l;
        }
    }
}

// ---------------- pc_w convert (coalesced): [co][ci][k] fp32 -> [kk][co][ci] bf16 hi/lo ----------------
__global__ __launch_bounds__(256) void convert_w2(const float* __restrict__ pcw) {
    extern __shared__ float ws[];    // [ci][81]
    int co = blockIdx.x;
    int t = threadIdx.x;
    const float* src = pcw + (size_t)co * 256 * 81;
    for (int idx = t; idx < 256 * 81; idx += 256) ws[idx] = src[idx];
    __syncthreads();
    int ci = t;
    for (int k = 0; k < 81; k++) {
        float v = ws[ci * 81 + k];
        __nv_bfloat16 h = __float2bfloat16(v);
        __nv_bfloat16 l = __float2bfloat16(v - __bfloat162float(h));
        size_t o = ((size_t)k * 256 + co) * 256 + ci;
        g_w2_hi[o] = h;
        g_w2_lo[o] = l;
    }
}

// ---------------- conv2 via HMMA implicit GEMM, cp.async double-buffered ----------------
#define LDK 72
#define BUFSZ 110592
#define AHI 0
#define ALO 18432
#define BHI 36864
#define BLO 73728
#define NITER 324
__global__ __launch_bounds__(256, 1) void conv2_mma(const float* __restrict__ pcb) {
    extern __shared__ char smem[];
    uint32_t sb = smem_u32(smem);
    int tid = threadIdx.x;
    int wid = tid >> 5;
    int lane = tid & 31;
    int mtile = blockIdx.x;      // 0..1   (co block of 128)
    int ntile = blockIdx.y;      // 0..71  (pos block of 256)

    int wm = wid & 3;
    int wn = wid >> 2;

    int seg = tid & 7;
    int rbase = tid >> 3;
    uint32_t adst[4];
    uint32_t aoff[4];
#pragma unroll
    for (int j = 0; j < 4; j++) {
        int row = rbase + j * 32;
        adst[j] = (uint32_t)(row * LDK + seg * 8) * 2;
        aoff[j] = (uint32_t)((mtile * 128 + row) * 256 + seg * 8);
    }
    uint32_t bdst[8];
    size_t gb[8];
#pragma unroll
    for (int j = 0; j < 8; j++) {
        int row = rbase + j * 32;
        bdst[j] = (uint32_t)(row * LDK + seg * 8) * 2;
        int p = ntile * 256 + row;
        int b = p / 36;
        int s = p - b * 36;
        int oh = s / 6, ow = s - oh * 6;
        gb[j] = ((size_t)b * 400 + oh * 40 + ow * 2) * 256 + seg * 8;
    }

    float acc[2][16][4];
#pragma unroll
    for (int mt = 0; mt < 2; mt++)
#pragma unroll
        for (int nt = 0; nt < 16; nt++)
#pragma unroll
            for (int j = 0; j < 4; j++) acc[mt][nt][j] = 0.f;

    int rowA = lane & 15;
    int kgA  = (lane >> 4) << 3;
    int rowB = ((lane >> 4) << 3) + (lane & 7);
    int kgB  = ((lane >> 3) & 1) << 3;

#define STAGE(IT, BSEL) do {                                                        \
        int _it = (IT);                                                             \
        int _cb = (_it / 81) << 6;                                                  \
        int _kk = _it - (_it / 81) * 81;                                            \
        int _kh = _kk / 9, _kw = _kk - _kh * 9;                                     \
        uint32_t _bu = sb + (BSEL) * BUFSZ;                                         \
        size_t _abase = ((size_t)_kk * 256) * 256 + _cb;                            \
        size_t _boff = (size_t)(_kh * 20 + _kw) * 256 + _cb;                        \
        _Pragma("unroll")                                                           \
        for (int j = 0; j < 4; j++) {                                               \
            size_t _s = _abase + aoff[j];                                           \
            cp16(_bu + AHI + adst[j], (const char*)g_w2_hi + _s * 2);               \
            cp16(_bu + ALO + adst[j], (const char*)g_w2_lo + _s * 2);               \
        }                                                                           \
        _Pragma("unroll")                                                           \
        for (int j = 0; j < 8; j++) {                                               \
            size_t _s = gb[j] + _boff;                                              \
            cp16(_bu + BHI + bdst[j], (const char*)g_h1_hi + _s * 2);               \
            cp16(_bu + BLO + bdst[j], (const char*)g_h1_lo + _s * 2);               \
        }                                                                           \
    } while (0)

    STAGE(0, 0);
    cp_commit();
    cp_wait0();
    __syncthreads();

    for (int it = 0; it < NITER; it++) {
        if (it + 1 < NITER) { STAGE(it + 1, (it + 1) & 1); cp_commit(); }

        uint32_t bu = sb + (it & 1) * BUFSZ;
#pragma unroll
        for (int ks = 0; ks < 4; ks++) {
            int k0 = ks * 16;
            uint32_t ahi[2][4], alo[2][4];
#pragma unroll
            for (int mt = 0; mt < 2; mt++) {
                uint32_t arow = (uint32_t)((wm * 32 + mt * 16 + rowA) * LDK + k0 + kgA) * 2;
                ldm_x4(ahi[mt], bu + AHI + arow);
                ldm_x4(alo[mt], bu + ALO + arow);
            }
#pragma unroll
            for (int nh = 0; nh < 4; nh++) {
                uint32_t bhi[4][2], blo[4][2];
#pragma unroll
                for (int nq = 0; nq < 2; nq++) {
                    uint32_t brow = (uint32_t)((wn * 128 + nh * 32 + nq * 16 + rowB) * LDK + k0 + kgB) * 2;
                    uint32_t t4[4];
                    ldm_x4(t4, bu + BHI + brow);
                    bhi[2 * nq][0] = t4[0]; bhi[2 * nq][1] = t4[1];
                    bhi[2 * nq + 1][0] = t4[2]; bhi[2 * nq + 1][1] = t4[3];
                    ldm_x4(t4, bu + BLO + brow);
                    blo[2 * nq][0] = t4[0]; blo[2 * nq][1] = t4[1];
                    blo[2 * nq + 1][0] = t4[2]; blo[2 * nq + 1][1] = t4[3];
                }
#pragma unroll
                for (int mt = 0; mt < 2; mt++)
#pragma unroll
                    for (int nq = 0; nq < 4; nq++) {
                        int nt = nh * 4 + nq;
                        mma_bf16(acc[mt][nt], ahi[mt], bhi[nq]);
                        mma_bf16(acc[mt][nt], ahi[mt], blo[nq]);
                        mma_bf16(acc[mt][nt], alo[mt], bhi[nq]);
                    }
            }
        }
        if (it + 1 < NITER) cp_wait0();
        __syncthreads();
    }

    int r0 = lane >> 2, cp = lane & 3;
#pragma unroll
    for (int mt = 0; mt < 2; mt++) {
#pragma unroll
        for (int half = 0; half < 2; half++) {
            int m = wm * 32 + mt * 16 + r0 + half * 8;
            int co = mtile * 128 + m;
            float bias = pcb[co];
#pragma unroll
            for (int nt = 0; nt < 16; nt++) {
#pragma unroll
                for (int e = 0; e < 2; e++) {
                    int p = ntile * 256 + wn * 128 + nt * 8 + 2 * cp + e;
                    int b = p / 36;
                    int s = p - b * 36;
                    g_h2[(size_t)b * 9216 + co * 36 + s] = acc[mt][nt][half * 2 + e] + bias;
                }
            }
        }
    }
}

// ---------------- squash over 8-dim capsules: g_h2 -> g_u ----------------
__global__ void squash_kernel() {
    int idx = blockIdx.x * 256 + threadIdx.x;
    if (idx >= 512 * 1152) return;
    const float4* p = (const float4*)(g_h2 + (size_t)idx * 8);
    float4 a = p[0], c = p[1];
    float n2 = a.x * a.x + a.y * a.y + a.z * a.z + a.w * a.w +
               c.x * c.x + c.y * c.y + c.z * c.z + c.w * c.w;
    float n = sqrtf(n2);
    float scale = n2 / (1.f + n2) / (n + 1e-8f);
    float4* q = (float4*)(g_u + (size_t)idx * 8);
    a.x *= scale; a.y *= scale; a.z *= scale; a.w *= scale;
    c.x *= scale; c.y *= scale; c.z *= scale; c.w *= scale;
    q[0] = a; q[1] = c;
}

// ---------------- votes, tiled: caps_w tile in smem, 64 b per block; fp16 output ----------------
__global__ __launch_bounds__(256) void xhat_kernel(const float* __restrict__ cw) {
    extern __shared__ float xsm[];
    float* ws = xsm;                    // 128 * 132
    float* us = xsm + 128 * 132;        // 1024

    int o  = blockIdx.x;
    int ic = blockIdx.y;
    int bc = blockIdx.z;
    int t  = threadIdx.x;

    const float4* src = (const float4*)(cw + ((size_t)o * 1152 + ic * 128) * 128);
    for (int j = t; j < 4096; j += 256) {
        float4 v = src[j];
        int fo = j * 4;
        int il = fo >> 7, rem = fo & 127;
        *(float4*)(ws + il * 132 + rem) = v;
    }
    __syncthreads();

    int d = t & 15;
    int tr = t >> 4;

    for (int bl = 0; bl < 64; bl++) {
        int b = bc * 64 + bl;
        const float4* up = (const float4*)(g_u + ((size_t)b * 1152 + ic * 128) * 8);
        __syncthreads();
        *(float4*)(us + t * 4) = up[t];
        __syncthreads();

        __half* xout = g_xhat + (((size_t)(b * 10 + o) * 1152) + ic * 128) * 16;
#pragma unroll
        for (int isub = 0; isub < 8; isub++) {
            int il = isub * 16 + tr;
            const float* wr = ws + il * 132 + d * 8;
            const float* ur = us + il * 8;
            float acc = wr[0] * ur[0] + wr[1] * ur[1] + wr[2] * ur[2] + wr[3] * ur[3]
                      + wr[4] * ur[4] + wr[5] * ur[5] + wr[6] * ur[6] + wr[7] * ur[7];
            xout[il * 16 + d] = __float2half(acc);
        }
    }
}

// ---------------- softmax over output caps: c[b,o,i] = softmax_o(blog[b,o,i]) ----------------
__global__ __launch_bounds__(256) void softmax_c(const float* __restrict__ blog) {
    int idx = blockIdx.x * 256 + threadIdx.x;   // b*1152 + i
    if (idx >= 512 * 1152) return;
    int b = idx / 1152, i = idx - b * 1152;
    const float* blb = blog + (size_t)b * 10 * 1152 + i;
    float vals[10];
    float m = -1e30f;
#pragma unroll
    for (int o = 0; o < 10; o++) {
        vals[o] = blb[(size_t)o * 1152];
        m = fmaxf(m, vals[o]);
    }
    float sum = 0.f;
#pragma unroll
    for (int o = 0; o < 10; o++) { vals[o] = expf(vals[o] - m); sum += vals[o]; }
    float inv = 1.f / sum;
    float* cb = g_c + (size_t)b * 10 * 1152 + i;
#pragma unroll
    for (int o = 0; o < 10; o++) cb[(size_t)o * 1152] = vals[o] * inv;
}

// ---------------- fused routing A+B: c -> v (squash) -> logit update (fp16 x_hat) ----------------
template <int MODE>
__global__ __launch_bounds__(256) void routeAB_kernel(const float* __restrict__ blin_g,
                                                      float* __restrict__ blout_g) {
    extern __shared__ float sm[];
    float* xs = sm;                 // [1152][17]
    float* cs = sm + 1152 * 17;     // [1152]
    __shared__ float sred[256];
    __shared__ float sd[16];
    __shared__ float sscale;

    int bo = blockIdx.x;
    int t = threadIdx.x;

    // load fp16 x_hat tile -> float smem (padded stride 17)
    const __half2* xg = (const __half2*)(g_xhat + (size_t)bo * 1152 * 16);
    for (int j = t; j < 1152 * 8; j += 256) {
        float2 f = __half22float2(xg[j]);
        int i = j >> 3, q = j & 7;
        float* dst = xs + i * 17 + q * 2;
        dst[0] = f.x; dst[1] = f.y;
    }

    if (MODE == 1) {
        const float* cg = g_c + (size_t)bo * 1152;
        for (int i = t; i < 1152; i += 256) cs[i] = cg[i];
    } else {
        for (int i = t; i < 1152; i += 256) cs[i] = 0.1f;
    }
    __syncthreads();

    int d = t & 15, g = t >> 4;
    float acc = 0.f;
    for (int i = g; i < 1152; i += 16)
        acc += cs[i] * xs[i * 17 + d];
    sred[t] = acc;
    __syncthreads();

    if (t < 16) {
        float s = 0.f;
#pragma unroll
        for (int gg = 0; gg < 16; gg++) s += sred[gg * 16 + t];
        sd[t] = s;
    }
    __syncthreads();

    if (t == 0) {
        float n2 = 0.f;
#pragma unroll
        for (int dd = 0; dd < 16; dd++) n2 += sd[dd] * sd[dd];
        float n = sqrtf(n2);
        sscale = n2 / (1.f + n2) / (n + 1e-8f);
    }
    __syncthreads();

    float scale = sscale;
    const float* blin = blin_g + (size_t)bo * 1152;
    float* blout = blout_g + (size_t)bo * 1152;
    for (int i = t; i < 1152; i += 256) {
        float dot = 0.f;
        const float* xr = xs + i * 17;
#pragma unroll
        for (int dd = 0; dd < 16; dd++) dot += sd[dd] * xr[dd];
        dot *= scale;
        blout[i] = (MODE == 1) ? (blin[i] + dot) : dot;
    }
}

// ---------------- final routing pass: c (precomputed) -> capsule lengths (fp16 x_hat) ----------------
__global__ __launch_bounds__(256) void routeFinal_kernel(float* __restrict__ out) {
    extern __shared__ float sm[];
    float* xs = sm;                 // [1152][17]
    float* cs = sm + 1152 * 17;     // [1152]
    __shared__ float sred[256];
    __shared__ float sd[16];

    int bo = blockIdx.x;
    int t = threadIdx.x;

    const __half2* xg = (const __half2*)(g_xhat + (size_t)bo * 1152 * 16);
    for (int j = t; j < 1152 * 8; j += 256) {
        float2 f = __half22float2(xg[j]);
        int i = j >> 3, q = j & 7;
        float* dst = xs + i * 17 + q * 2;
        dst[0] = f.x; dst[1] = f.y;
    }
    const float* cg = g_c + (size_t)bo * 1152;
    for (int i = t; i < 1152; i += 256) cs[i] = cg[i];
    __syncthreads();

    int d = t & 15, g = t >> 4;
    float acc = 0.f;
    for (int i = g; i < 1152; i += 16)
        acc += cs[i] * xs[i * 17 + d];
    sred[t] = acc;
    __syncthreads();

    if (t < 16) {
        float s = 0.f;
#pragma unroll
        for (int gg = 0; gg < 16; gg++) s += sred[gg * 16 + t];
        sd[t] = s;
    }
    __syncthreads();

    if (t == 0) {
        float n2 = 0.f;
#pragma unroll
        for (int dd = 0; dd < 16; dd++) n2 += sd[dd] * sd[dd];
        float n = sqrtf(n2);
        float scale = n2 / (1.f + n2) / (n + 1e-8f);
        out[bo] = scale * n;
    }
}

// ---------------- launch ----------------
extern "C" void kernel_launch(void* const* d_in, const int* in_sizes, int n_in,
                              void* d_out, int out_size) {
    const float* x   = (const float*)d_in[0];
    const float* w1  = (const float*)d_in[1];
    const float* b1  = (const float*)d_in[2];
    const float* w2  = (const float*)d_in[3];
    const float* b2  = (const float*)d_in[4];
    const float* cw  = (const float*)d_in[5];
    float* out = (float*)d_out;

    const int CONV2_SMEM = 2 * BUFSZ;                    // 221184 B
    const int ROUTE_SMEM = (1152 * 17 + 1152) * 4;       // 82944 B
    const int W2_SMEM    = 256 * 81 * 4;                 // 82944 B
    const int XHAT_SMEM  = (128 * 132 + 1024) * 4;       // 71680 B
    cudaFuncSetAttribute(conv2_mma, cudaFuncAttributeMaxDynamicSharedMemorySize, CONV2_SMEM);
    cudaFuncSetAttribute(convert_w2, cudaFuncAttributeMaxDynamicSharedMemorySize, W2_SMEM);
    cudaFuncSetAttribute(xhat_kernel, cudaFuncAttributeMaxDynamicSharedMemorySize, XHAT_SMEM);
    cudaFuncSetAttribute(routeAB_kernel<0>, cudaFuncAttributeMaxDynamicSharedMemorySize, ROUTE_SMEM);
    cudaFuncSetAttribute(routeAB_kernel<1>, cudaFuncAttributeMaxDynamicSharedMemorySize, ROUTE_SMEM);
    cudaFuncSetAttribute(routeFinal_kernel, cudaFuncAttributeMaxDynamicSharedMemorySize, ROUTE_SMEM);

    float *blog0, *blog1;
    cudaGetSymbolAddress((void**)&blog0, g_blog0);
    cudaGetSymbolAddress((void**)&blog1, g_blog1);

    conv1_kernel<<<dim3(512, 2), 256>>>(x, w1, b1);
    convert_w2<<<256, 256, W2_SMEM>>>(w2);
    conv2_mma<<<dim3(2, 72), 256, CONV2_SMEM>>>(b2);
    squash_kernel<<<(512 * 1152 + 255) / 256, 256>>>();
    xhat_kernel<<<dim3(10, 9, 8), 256, XHAT_SMEM>>>(cw);

    routeAB_kernel<0><<<5120, 256, ROUTE_SMEM>>>(blog0, blog0);   // iter 0: uniform c
    softmax_c<<<(512 * 1152 + 255) / 256, 256>>>(blog0);
    routeAB_kernel<1><<<5120, 256, ROUTE_SMEM>>>(blog0, blog1);   // iter 1
    softmax_c<<<(512 * 1152 + 255) / 256, 256>>>(blog1);
    routeFinal_kernel<<<5120, 256, ROUTE_SMEM>>>(out);            // iter 2: lengths
}